// round 1
// baseline (speedup 1.0000x reference)
#include <cuda_runtime.h>
#include <cstdint>
#include <cstddef>

#define NB 64
#define NT 512
#define NH 1024
#define GRID2 128

#define GATE_STRIDE 33554432u  // 512*64*1024

// Scratch (static device allocations are the sanctioned path)
__device__ float g_gates[4u * GATE_STRIDE];   // [gate][t][b][h], 512 MB
__device__ float g_hbuf[2][NB * NH];          // double-buffered h state
__device__ unsigned g_arrive;
__device__ volatile unsigned g_release;

__device__ __forceinline__ unsigned f2tf(float f) {
    unsigned r;
    asm("cvt.rna.tf32.f32 %0, %1;" : "=r"(r) : "f"(f));
    return r;
}

__device__ __forceinline__ void mma8(float c[4], const unsigned a[4], const unsigned b[2]) {
    asm volatile(
        "mma.sync.aligned.m16n8k8.row.col.f32.tf32.tf32.f32 "
        "{%0,%1,%2,%3},{%4,%5,%6,%7},{%8,%9},{%0,%1,%2,%3};\n"
        : "+f"(c[0]), "+f"(c[1]), "+f"(c[2]), "+f"(c[3])
        : "r"(a[0]), "r"(a[1]), "r"(a[2]), "r"(a[3]), "r"(b[0]), "r"(b[1]));
}

// ---------------------------------------------------------------------------
// Init: reset h0 and barrier state (must run every graph replay)
// ---------------------------------------------------------------------------
__global__ void init_k() {
    unsigned i = blockIdx.x * blockDim.x + threadIdx.x;
    if (i < NB * NH) g_hbuf[0][i] = 0.0f;
    if (i == 0) { g_arrive = 0u; g_release = 0u; }
}

// ---------------------------------------------------------------------------
// Phase 1: gate preactivations  g_gates[g][t][b][h] = x @ W_xg + b_g
// GEMM M=32768 (b*512+t), N=4096 (4 gates x 1024), K=1024. tf32 MMA.
// Block tile 128x128x32, 256 threads, warp tile 64x32.
// ---------------------------------------------------------------------------
#define P1_SA 36
#define P1_SB 136

__global__ void __launch_bounds__(256) lstm_xproj(
    const float* __restrict__ x,
    const float* __restrict__ Wxi, const float* __restrict__ Wxf,
    const float* __restrict__ Wxc, const float* __restrict__ Wxo,
    const float* __restrict__ bi,  const float* __restrict__ bf,
    const float* __restrict__ bc,  const float* __restrict__ bo)
{
    __shared__ unsigned Asm[128 * P1_SA];
    __shared__ unsigned Bsm[32 * P1_SB];

    const int tid  = threadIdx.x;
    const int lane = tid & 31;
    const int w    = tid >> 5;
    const int mi   = w & 1;   // m base = mi*64
    const int nj   = w >> 1;  // n base = nj*32

    const int mblk  = blockIdx.y;
    const int nglob = blockIdx.x * 128;
    const int gate  = nglob >> 10;
    const int hbase = nglob & 1023;

    const float* W    = (gate == 0) ? Wxi : (gate == 1) ? Wxf : (gate == 2) ? Wxc : Wxo;
    const float* bias = (gate == 0) ? bi  : (gate == 1) ? bf  : (gate == 2) ? bc  : bo;

    float acc[4][4][4];
#pragma unroll
    for (int a = 0; a < 4; a++)
#pragma unroll
        for (int b = 0; b < 4; b++)
#pragma unroll
            for (int c = 0; c < 4; c++) acc[a][b][c] = 0.0f;

    for (int kt = 0; kt < 1024 / 32; ++kt) {
        // load A tile: 128 rows x 32 cols of x
#pragma unroll
        for (int i = 0; i < 4; i++) {
            int f   = tid + 256 * i;          // 0..1023
            int row = f >> 3, c4 = f & 7;
            const float4 v = *(const float4*)(x + (size_t)(mblk * 128 + row) * 1024 + kt * 32 + c4 * 4);
            unsigned* d = &Asm[row * P1_SA + c4 * 4];
            d[0] = f2tf(v.x); d[1] = f2tf(v.y); d[2] = f2tf(v.z); d[3] = f2tf(v.w);
        }
        // load B tile: 32 k-rows x 128 cols of W
#pragma unroll
        for (int i = 0; i < 4; i++) {
            int f = tid + 256 * i;            // 0..1023
            int k = f >> 5, c4 = f & 31;
            const float4 v = *(const float4*)(W + (size_t)(kt * 32 + k) * 1024 + hbase + c4 * 4);
            unsigned* d = &Bsm[k * P1_SB + c4 * 4];
            d[0] = f2tf(v.x); d[1] = f2tf(v.y); d[2] = f2tf(v.z); d[3] = f2tf(v.w);
        }
        __syncthreads();

#pragma unroll
        for (int q = 0; q < 4; q++) {
            const int kk = q * 8;
            unsigned afr[4][4], bfr[4][2];
#pragma unroll
            for (int mt = 0; mt < 4; mt++) {
                int r = mi * 64 + mt * 16 + (lane >> 2);
                int c = kk + (lane & 3);
                afr[mt][0] = Asm[r * P1_SA + c];
                afr[mt][1] = Asm[(r + 8) * P1_SA + c];
                afr[mt][2] = Asm[r * P1_SA + c + 4];
                afr[mt][3] = Asm[(r + 8) * P1_SA + c + 4];
            }
#pragma unroll
            for (int nt = 0; nt < 4; nt++) {
                int nb = nj * 32 + nt * 8 + (lane >> 2);
                int kr = kk + (lane & 3);
                bfr[nt][0] = Bsm[kr * P1_SB + nb];
                bfr[nt][1] = Bsm[(kr + 4) * P1_SB + nb];
            }
#pragma unroll
            for (int mt = 0; mt < 4; mt++)
#pragma unroll
                for (int nt = 0; nt < 4; nt++)
                    mma8(acc[mt][nt], afr[mt], bfr[nt]);
        }
        __syncthreads();
    }

    // epilogue: add bias, scatter to time-major gate buffer
    float* gbuf = g_gates + (size_t)gate * GATE_STRIDE;
#pragma unroll
    for (int mt = 0; mt < 4; mt++) {
#pragma unroll
        for (int nt = 0; nt < 4; nt++) {
#pragma unroll
            for (int rr = 0; rr < 2; rr++) {
                int m   = mblk * 128 + mi * 64 + mt * 16 + (lane >> 2) + rr * 8;
                int col = nj * 32 + nt * 8 + (lane & 3) * 2;
                int h   = hbase + col;
                int b   = m >> 9;       // batch
                int t   = m & 511;      // timestep
                float2 o;
                o.x = acc[mt][nt][rr * 2 + 0] + __ldg(bias + h);
                o.y = acc[mt][nt][rr * 2 + 1] + __ldg(bias + h + 1);
                *(float2*)(gbuf + (size_t)t * 65536 + (size_t)b * 1024 + h) = o;
            }
        }
    }
}

// ---------------------------------------------------------------------------
// Phase 2: persistent recurrence. 128 CTAs, CTA owns h-cols [blk*8, blk*8+8)
// across all 4 gates (N=32). W_h slice stays in SMEM for all 512 steps.
// One grid barrier per step; h double-buffered in global.
// ---------------------------------------------------------------------------
#define P2_SW 40     // Wsm stride (words)   -> conflict-free b-fragments
#define P2_SA 132    // Asm stride (KT=128)  -> conflict-free a-fragments
#define P2_SZ 36

#define SMEM2_BYTES ((1024 * P2_SW + 64 * P2_SA + 64 * P2_SZ + 512) * 4)

__global__ void __launch_bounds__(256) lstm_rec(
    const float* __restrict__ Whi, const float* __restrict__ Whf,
    const float* __restrict__ Whc, const float* __restrict__ Who,
    float* __restrict__ out)
{
    extern __shared__ unsigned char smem_raw[];
    unsigned* Wsm  = (unsigned*)smem_raw;            // [1024][40]
    unsigned* AsmU = Wsm + 1024 * P2_SW;             // [64][132]
    float*    zsm  = (float*)(AsmU + 64 * P2_SA);    // [64][36]
    float*    csm  = zsm + 64 * P2_SZ;               // [64][8]

    const int tid  = threadIdx.x;
    const int lane = tid & 31;
    const int w    = tid >> 5;
    const int mi   = w & 3;    // m base = mi*16
    const int nj   = w >> 2;   // n base = nj*16
    const int blk  = blockIdx.x;
    const int hb   = blk * 8;

    // Load weight slice into SMEM (once), tf32-converted.
    {
        const float* Wg[4] = {Whi, Whf, Whc, Who};
        for (int idx = tid; idx < 4096; idx += 256) {
            int g = idx >> 10, k = idx & 1023;
            const float* src = Wg[g] + (size_t)k * 1024 + hb;
            float4 v0 = *(const float4*)(src);
            float4 v1 = *(const float4*)(src + 4);
            unsigned* d = &Wsm[k * P2_SW + g * 8];
            d[0] = f2tf(v0.x); d[1] = f2tf(v0.y); d[2] = f2tf(v0.z); d[3] = f2tf(v0.w);
            d[4] = f2tf(v1.x); d[5] = f2tf(v1.y); d[6] = f2tf(v1.z); d[7] = f2tf(v1.w);
        }
        for (int i = tid; i < 512; i += 256) csm[i] = 0.0f;
    }
    __syncthreads();

    for (int t = 0; t < NT; ++t) {
        const float* hprev = g_hbuf[t & 1];
        float*       hnext = g_hbuf[(t + 1) & 1];

        float acc[2][4];
#pragma unroll
        for (int a = 0; a < 2; a++)
#pragma unroll
            for (int c = 0; c < 4; c++) acc[a][c] = 0.0f;

        for (int kt = 0; kt < 8; ++kt) {          // K tiles of 128
            __syncthreads();                      // protect Asm reuse
            // load h tile [64 x 128], bypass L1 (cross-SM producer)
#pragma unroll
            for (int i = 0; i < 8; i++) {
                int f   = tid + 256 * i;          // 0..2047
                int row = f >> 5, c4 = f & 31;
                float4 v = __ldcg((const float4*)(hprev + row * 1024 + kt * 128 + c4 * 4));
                unsigned* d = &AsmU[row * P2_SA + c4 * 4];
                d[0] = f2tf(v.x); d[1] = f2tf(v.y); d[2] = f2tf(v.z); d[3] = f2tf(v.w);
            }
            __syncthreads();

#pragma unroll
            for (int q = 0; q < 16; q++) {
                const int kk = q * 8;
                unsigned afr[4];
                int r = mi * 16 + (lane >> 2);
                afr[0] = AsmU[r * P2_SA + kk + (lane & 3)];
                afr[1] = AsmU[(r + 8) * P2_SA + kk + (lane & 3)];
                afr[2] = AsmU[r * P2_SA + kk + (lane & 3) + 4];
                afr[3] = AsmU[(r + 8) * P2_SA + kk + (lane & 3) + 4];
                int kglob = kt * 128 + kk + (lane & 3);
#pragma unroll
                for (int nt = 0; nt < 2; nt++) {
                    int nb = nj * 16 + nt * 8 + (lane >> 2);
                    unsigned bfr[2];
                    bfr[0] = Wsm[kglob * P2_SW + nb];
                    bfr[1] = Wsm[(kglob + 4) * P2_SW + nb];
                    mma8(acc[nt], afr, bfr);
                }
            }
        }

        // gather z into SMEM so every thread can see all 4 gates
        __syncthreads();
#pragma unroll
        for (int nt = 0; nt < 2; nt++) {
#pragma unroll
            for (int rr = 0; rr < 2; rr++) {
                int r = mi * 16 + (lane >> 2) + rr * 8;
                int c = nj * 16 + nt * 8 + (lane & 3) * 2;
                zsm[r * P2_SZ + c]     = acc[nt][rr * 2 + 0];
                zsm[r * P2_SZ + c + 1] = acc[nt][rr * 2 + 1];
            }
        }
        __syncthreads();

        // elementwise LSTM cell update: 512 elements, 2 per thread
#pragma unroll
        for (int s = 0; s < 2; s++) {
            int e = tid + 256 * s;
            int m = e >> 3, j = e & 7;
            int hcol = hb + j;
            size_t gidx = (size_t)t * 65536 + (size_t)m * 1024 + hcol;
            float zi = zsm[m * P2_SZ + j]      + __ldg(g_gates + gidx);
            float zf = zsm[m * P2_SZ + 8 + j]  + __ldg(g_gates + GATE_STRIDE + gidx);
            float zc = zsm[m * P2_SZ + 16 + j] + __ldg(g_gates + 2u * GATE_STRIDE + gidx);
            float zo = zsm[m * P2_SZ + 24 + j] + __ldg(g_gates + 3u * GATE_STRIDE + gidx);
            float iv = 1.0f / (1.0f + expf(-zi));
            float fv = 1.0f / (1.0f + expf(-zf));
            float cv = tanhf(zc);
            float ov = 1.0f / (1.0f + expf(-zo));
            float cold = csm[e];
            float cnew = fv * cold + iv * cv;
            csm[e] = cnew;
            float hv = ov * tanhf(cnew);
            hnext[m * 1024 + hcol] = hv;
            out[(size_t)m * 524288 + (size_t)t * 1024 + hcol] = hv;
            if (t == NT - 1) {
                out[33554432u + (size_t)m * 1024 + hcol] = hv;            // h_T
                out[33554432u + 65536u + (size_t)m * 1024 + hcol] = cnew; // c_T
            }
        }

        // ---- grid barrier (epoch t+1) ----
        __syncthreads();
        if (tid == 0) {
            __threadfence();
            unsigned arrived = atomicAdd(&g_arrive, 1u) + 1u;
            unsigned epoch   = (unsigned)(t + 1);
            if (arrived == epoch * GRID2) {
                g_release = epoch;
            } else {
                while (g_release < epoch) { }
            }
            __threadfence();
        }
        __syncthreads();
    }
}

// ---------------------------------------------------------------------------
extern "C" void kernel_launch(void* const* d_in, const int* in_sizes, int n_in,
                              void* d_out, int out_size)
{
    const float* x   = (const float*)d_in[0];
    const float* Wxi = (const float*)d_in[1];
    const float* Whi = (const float*)d_in[2];
    const float* bi  = (const float*)d_in[3];
    const float* Wxf = (const float*)d_in[4];
    const float* Whf = (const float*)d_in[5];
    const float* bf  = (const float*)d_in[6];
    const float* Wxc = (const float*)d_in[7];
    const float* Whc = (const float*)d_in[8];
    const float* bc  = (const float*)d_in[9];
    const float* Wxo = (const float*)d_in[10];
    const float* Who = (const float*)d_in[11];
    const float* bo  = (const float*)d_in[12];
    float* out = (float*)d_out;

    cudaFuncSetAttribute(lstm_rec, cudaFuncAttributeMaxDynamicSharedMemorySize, SMEM2_BYTES);

    init_k<<<256, 256>>>();

    dim3 g1(32, 256);     // 32 n-tiles (4096/128), 256 m-tiles (32768/128)
    lstm_xproj<<<g1, 256>>>(x, Wxi, Wxf, Wxc, Wxo, bi, bf, bc, bo);

    lstm_rec<<<GRID2, 256, SMEM2_BYTES>>>(Whi, Whf, Whc, Who, out);
}

// round 2
// speedup vs baseline: 1.6544x; 1.6544x over previous
#include <cuda_runtime.h>
#include <cstdint>
#include <cstddef>

#define NB 64
#define NT 512
#define NH 1024
#define GRID2 128

#define GATE_STRIDE 33554432u  // 512*64*1024

__device__ float g_gates[4u * GATE_STRIDE];   // [gate][t][b][h]
__device__ float g_hbuf[2][NB * NH];          // double-buffered h state
__device__ unsigned g_flags[GRID2 * 8];       // per-CTA barrier flags (32B apart)

__device__ __forceinline__ unsigned f2tf(float f) {
    unsigned r;
    asm("cvt.rna.tf32.f32 %0, %1;" : "=r"(r) : "f"(f));
    return r;
}

__device__ __forceinline__ void mma8(float c[4], const unsigned a[4], const unsigned b[2]) {
    asm volatile(
        "mma.sync.aligned.m16n8k8.row.col.f32.tf32.tf32.f32 "
        "{%0,%1,%2,%3},{%4,%5,%6,%7},{%8,%9},{%0,%1,%2,%3};\n"
        : "+f"(c[0]), "+f"(c[1]), "+f"(c[2]), "+f"(c[3])
        : "r"(a[0]), "r"(a[1]), "r"(a[2]), "r"(a[3]), "r"(b[0]), "r"(b[1]));
}

__device__ __forceinline__ void cp16(unsigned dst, const float* src) {
    asm volatile("cp.async.ca.shared.global [%0], [%1], 16;\n" :: "r"(dst), "l"(src));
}

// ---------------------------------------------------------------------------
// Phase 1: gate preactivations  g_gates[g][t][b][h] = x @ W_xg + b_g
// M=32768, N=4096 (4 gates x 1024), K=1024. cp.async double-buffered.
// Block tile 128x128x32, 256 threads, warp tile 64x32. Raw f32 in smem,
// tf32 convert at fragment load. Block (0,0) also does per-replay init.
// ---------------------------------------------------------------------------
#define P1_SA 36
#define P1_SB 136
#define P1_SMEM ((2 * 128 * P1_SA + 2 * 32 * P1_SB) * 4)

__global__ void __launch_bounds__(256, 2) lstm_xproj(
    const float* __restrict__ x,
    const float* __restrict__ Wxi, const float* __restrict__ Wxf,
    const float* __restrict__ Wxc, const float* __restrict__ Wxo,
    const float* __restrict__ bi,  const float* __restrict__ bf,
    const float* __restrict__ bc,  const float* __restrict__ bo)
{
    extern __shared__ float p1s[];
    float* As = p1s;                        // [2][128][P1_SA]
    float* Bs = p1s + 2 * 128 * P1_SA;      // [2][32][P1_SB]

    const int tid  = threadIdx.x;

    // per-replay init (h0 = 0, barrier flags = 0), done by one block
    if (blockIdx.x == 0 && blockIdx.y == 0) {
        float4 z4 = make_float4(0.f, 0.f, 0.f, 0.f);
        float4* hb4 = (float4*)g_hbuf[0];
#pragma unroll 4
        for (int i = tid; i < (NB * NH) / 4; i += 256) hb4[i] = z4;
        for (int i = tid; i < GRID2 * 8; i += 256) g_flags[i] = 0u;
    }

    const int lane = tid & 31;
    const int w    = tid >> 5;
    const int mi   = w & 1;   // m base = mi*64
    const int nj   = w >> 1;  // n base = nj*32

    const int mblk  = blockIdx.y;
    const int nglob = blockIdx.x * 128;
    const int gate  = nglob >> 10;
    const int hbase = nglob & 1023;

    const float* W    = (gate == 0) ? Wxi : (gate == 1) ? Wxf : (gate == 2) ? Wxc : Wxo;
    const float* bias = (gate == 0) ? bi  : (gate == 1) ? bf  : (gate == 2) ? bc  : bo;

    // per-thread copy coordinates
    const int a_row = tid >> 3, a_c4 = tid & 7;       // + 32 rows per i
    const int b_k   = tid >> 5, b_c4 = tid & 31;      // + 8 k per i
    const unsigned As_u = (unsigned)__cvta_generic_to_shared(As);
    const unsigned Bs_u = (unsigned)__cvta_generic_to_shared(Bs);

    float acc[4][4][4];
#pragma unroll
    for (int a = 0; a < 4; a++)
#pragma unroll
        for (int b = 0; b < 4; b++)
#pragma unroll
            for (int c = 0; c < 4; c++) acc[a][b][c] = 0.0f;

    // prefetch tile 0
    {
#pragma unroll
        for (int i = 0; i < 4; i++) {
            int row = a_row + 32 * i;
            cp16(As_u + (row * P1_SA + a_c4 * 4) * 4,
                 x + (size_t)(mblk * 128 + row) * 1024 + a_c4 * 4);
            int k = b_k + 8 * i;
            cp16(Bs_u + (k * P1_SB + b_c4 * 4) * 4,
                 W + (size_t)k * 1024 + hbase + b_c4 * 4);
        }
        asm volatile("cp.async.commit_group;\n");
    }

#pragma unroll 1
    for (int kt = 0; kt < 32; ++kt) {
        asm volatile("cp.async.wait_group 0;\n");
        __syncthreads();

        if (kt + 1 < 32) {
            int s = (kt + 1) & 1;
#pragma unroll
            for (int i = 0; i < 4; i++) {
                int row = a_row + 32 * i;
                cp16(As_u + (s * 128 * P1_SA + row * P1_SA + a_c4 * 4) * 4,
                     x + (size_t)(mblk * 128 + row) * 1024 + (kt + 1) * 32 + a_c4 * 4);
                int k = b_k + 8 * i;
                cp16(Bs_u + (s * 32 * P1_SB + k * P1_SB + b_c4 * 4) * 4,
                     W + (size_t)((kt + 1) * 32 + k) * 1024 + hbase + b_c4 * 4);
            }
            asm volatile("cp.async.commit_group;\n");
        }

        const float* Ab = As + (kt & 1) * 128 * P1_SA;
        const float* Bb = Bs + (kt & 1) * 32 * P1_SB;

#pragma unroll
        for (int q = 0; q < 4; q++) {
            const int kk = q * 8;
            unsigned afr[4][4], bfr[4][2];
#pragma unroll
            for (int mt = 0; mt < 4; mt++) {
                int r = mi * 64 + mt * 16 + (lane >> 2);
                int c = kk + (lane & 3);
                afr[mt][0] = f2tf(Ab[r * P1_SA + c]);
                afr[mt][1] = f2tf(Ab[(r + 8) * P1_SA + c]);
                afr[mt][2] = f2tf(Ab[r * P1_SA + c + 4]);
                afr[mt][3] = f2tf(Ab[(r + 8) * P1_SA + c + 4]);
            }
#pragma unroll
            for (int nt = 0; nt < 4; nt++) {
                int nb = nj * 32 + nt * 8 + (lane >> 2);
                int kr = kk + (lane & 3);
                bfr[nt][0] = f2tf(Bb[kr * P1_SB + nb]);
                bfr[nt][1] = f2tf(Bb[(kr + 4) * P1_SB + nb]);
            }
#pragma unroll
            for (int mt = 0; mt < 4; mt++)
#pragma unroll
                for (int nt = 0; nt < 4; nt++)
                    mma8(acc[mt][nt], afr[mt], bfr[nt]);
        }
    }

    // epilogue: add bias, scatter to time-major gate buffer
    float* gbuf = g_gates + (size_t)gate * GATE_STRIDE;
#pragma unroll
    for (int mt = 0; mt < 4; mt++) {
#pragma unroll
        for (int nt = 0; nt < 4; nt++) {
#pragma unroll
            for (int rr = 0; rr < 2; rr++) {
                int m   = mblk * 128 + mi * 64 + mt * 16 + (lane >> 2) + rr * 8;
                int col = nj * 32 + nt * 8 + (lane & 3) * 2;
                int h   = hbase + col;
                int b   = m >> 9;
                int t   = m & 511;
                float2 o;
                o.x = acc[mt][nt][rr * 2 + 0] + __ldg(bias + h);
                o.y = acc[mt][nt][rr * 2 + 1] + __ldg(bias + h + 1);
                *(float2*)(gbuf + (size_t)t * 65536 + (size_t)b * 1024 + h) = o;
            }
        }
    }
}

// ---------------------------------------------------------------------------
// Phase 2: persistent recurrence. 128 CTAs x 512 threads. CTA owns h-cols
// [blk*8, blk*8+8) across 4 gates (N=32). W_h slice resident in SMEM.
// 16 warps: 4 m-tiles x 4 K-groups (K split 4-way, warp tile m16 n32).
// h streamed in 64-wide double-buffered chunks, one sync per chunk.
// ---------------------------------------------------------------------------
#define P2_SW 40
#define P2_SA 68
#define P2_SZ 36
#define SMEM2_BYTES ((1024 * P2_SW + 2 * 64 * P2_SA + 2 * 64 * P2_SZ + 512) * 4)

__global__ void __launch_bounds__(512, 1) lstm_rec(
    const float* __restrict__ Whi, const float* __restrict__ Whf,
    const float* __restrict__ Whc, const float* __restrict__ Who,
    float* __restrict__ out)
{
    extern __shared__ unsigned char smem_raw[];
    unsigned* Wsm = (unsigned*)smem_raw;               // [1024][P2_SW]
    unsigned* Asm = Wsm + 1024 * P2_SW;                // [2][64][P2_SA]
    float*    zsm = (float*)(Asm + 2 * 64 * P2_SA);    // [2][64][P2_SZ]
    float*    csm = zsm + 2 * 64 * P2_SZ;              // [512]

    const int tid  = threadIdx.x;
    const int lane = tid & 31;
    const int w    = tid >> 5;
    const int mi   = w & 3;    // m base = mi*16
    const int ks   = w >> 2;   // K group: k in [chunk*64 + ks*16, +16)
    const int blk  = blockIdx.x;
    const int hb   = blk * 8;

    // weight slice -> SMEM (tf32), once
    {
        const float* Wg[4] = {Whi, Whf, Whc, Who};
        for (int idx = tid; idx < 4096; idx += 512) {
            int g = idx >> 10, k = idx & 1023;
            const float* src = Wg[g] + (size_t)k * 1024 + hb;
            float4 v0 = *(const float4*)(src);
            float4 v1 = *(const float4*)(src + 4);
            unsigned* d = &Wsm[k * P2_SW + g * 8];
            d[0] = f2tf(v0.x); d[1] = f2tf(v0.y); d[2] = f2tf(v0.z); d[3] = f2tf(v0.w);
            d[4] = f2tf(v1.x); d[5] = f2tf(v1.y); d[6] = f2tf(v1.z); d[7] = f2tf(v1.w);
        }
        csm[tid] = 0.0f;
    }
    __syncthreads();

    // chunk-copy coordinates: 64 rows x 64 cols, 512 threads x 2 float4
    const int cr0 = tid >> 4, cc0 = tid & 15;          // rows 0..31
    const int cr1 = cr0 + 32;                           // rows 32..63
    // elementwise coordinates
    const int em = tid >> 3, ej = tid & 7;
    const int hcol = hb + ej;

#pragma unroll 1
    for (int t = 0; t < NT; ++t) {
        const float* hprev = g_hbuf[t & 1];
        float*       hnext = g_hbuf[(t + 1) & 1];

        // prefetch this step's gate preactivations (DRAM latency hidden by GEMM)
        const size_t gidx = (size_t)t * 65536 + (size_t)em * 1024 + hcol;
        const float gi = __ldg(g_gates + gidx);
        const float gf = __ldg(g_gates + GATE_STRIDE + gidx);
        const float gc = __ldg(g_gates + 2u * GATE_STRIDE + gidx);
        const float go = __ldg(g_gates + 3u * GATE_STRIDE + gidx);

        float acc[4][4];
#pragma unroll
        for (int a = 0; a < 4; a++)
#pragma unroll
            for (int c = 0; c < 4; c++) acc[a][c] = 0.0f;

        // preload chunk 0 -> buf 0
        {
            float4 v0 = __ldcg((const float4*)(hprev + cr0 * 1024 + cc0 * 4));
            float4 v1 = __ldcg((const float4*)(hprev + cr1 * 1024 + cc0 * 4));
            uint4 u0 = make_uint4(f2tf(v0.x), f2tf(v0.y), f2tf(v0.z), f2tf(v0.w));
            uint4 u1 = make_uint4(f2tf(v1.x), f2tf(v1.y), f2tf(v1.z), f2tf(v1.w));
            *(uint4*)&Asm[cr0 * P2_SA + cc0 * 4] = u0;
            *(uint4*)&Asm[cr1 * P2_SA + cc0 * 4] = u1;
        }
        __syncthreads();

#pragma unroll 1
        for (int ch = 0; ch < 16; ++ch) {
            float4 v0, v1;
            const bool more = (ch + 1 < 16);
            if (more) {
                v0 = __ldcg((const float4*)(hprev + cr0 * 1024 + (ch + 1) * 64 + cc0 * 4));
                v1 = __ldcg((const float4*)(hprev + cr1 * 1024 + (ch + 1) * 64 + cc0 * 4));
            }

            const unsigned* Ab = Asm + (ch & 1) * 64 * P2_SA;
#pragma unroll
            for (int q = 0; q < 2; q++) {
                const int kloc = ks * 16 + q * 8 + (lane & 3);
                const int r    = mi * 16 + (lane >> 2);
                unsigned afr[4];
                afr[0] = Ab[r * P2_SA + kloc];
                afr[1] = Ab[(r + 8) * P2_SA + kloc];
                afr[2] = Ab[r * P2_SA + kloc + 4];
                afr[3] = Ab[(r + 8) * P2_SA + kloc + 4];
                const int kg = ch * 64 + kloc;
#pragma unroll
                for (int nt = 0; nt < 4; nt++) {
                    const int nb = nt * 8 + (lane >> 2);
                    unsigned bfr[2];
                    bfr[0] = Wsm[kg * P2_SW + nb];
                    bfr[1] = Wsm[(kg + 4) * P2_SW + nb];
                    mma8(acc[nt], afr, bfr);
                }
            }

            if (more) {
                unsigned* Aw = Asm + ((ch + 1) & 1) * 64 * P2_SA;
                uint4 u0 = make_uint4(f2tf(v0.x), f2tf(v0.y), f2tf(v0.z), f2tf(v0.w));
                uint4 u1 = make_uint4(f2tf(v1.x), f2tf(v1.y), f2tf(v1.z), f2tf(v1.w));
                *(uint4*)&Aw[cr0 * P2_SA + cc0 * 4] = u0;
                *(uint4*)&Aw[cr1 * P2_SA + cc0 * 4] = u1;
            }
            __syncthreads();
        }

        // K-group reduction: ks0/ks1 store into zsm[0]/zsm[1]; ks2/ks3 add
        if (ks < 2) {
            float* z = zsm + ks * 64 * P2_SZ;
#pragma unroll
            for (int nt = 0; nt < 4; nt++)
#pragma unroll
                for (int rr = 0; rr < 2; rr++) {
                    int r = mi * 16 + (lane >> 2) + rr * 8;
                    int c = nt * 8 + (lane & 3) * 2;
                    z[r * P2_SZ + c]     = acc[nt][rr * 2 + 0];
                    z[r * P2_SZ + c + 1] = acc[nt][rr * 2 + 1];
                }
        }
        __syncthreads();
        if (ks >= 2) {
            float* z = zsm + (ks - 2) * 64 * P2_SZ;
#pragma unroll
            for (int nt = 0; nt < 4; nt++)
#pragma unroll
                for (int rr = 0; rr < 2; rr++) {
                    int r = mi * 16 + (lane >> 2) + rr * 8;
                    int c = nt * 8 + (lane & 3) * 2;
                    z[r * P2_SZ + c]     += acc[nt][rr * 2 + 0];
                    z[r * P2_SZ + c + 1] += acc[nt][rr * 2 + 1];
                }
        }
        __syncthreads();

        // elementwise LSTM cell update: one element per thread
        {
            const float* z0 = zsm + em * P2_SZ;
            const float* z1 = zsm + 64 * P2_SZ + em * P2_SZ;
            float zi = z0[ej]      + z1[ej]      + gi;
            float zf = z0[8 + ej]  + z1[8 + ej]  + gf;
            float zc = z0[16 + ej] + z1[16 + ej] + gc;
            float zo = z0[24 + ej] + z1[24 + ej] + go;
            float iv = 1.0f / (1.0f + __expf(-zi));
            float fv = 1.0f / (1.0f + __expf(-zf));
            float cv = tanhf(zc);
            float ov = 1.0f / (1.0f + __expf(-zo));
            float cnew = fv * csm[tid] + iv * cv;
            csm[tid] = cnew;
            float hv = ov * tanhf(cnew);
            hnext[em * 1024 + hcol] = hv;
            out[(size_t)em * 524288 + (size_t)t * 1024 + hcol] = hv;
            if (t == NT - 1) {
                out[33554432u + (size_t)em * 1024 + hcol] = hv;
                out[33554432u + 65536u + (size_t)em * 1024 + hcol] = cnew;
            }
        }

        // ---- distributed grid barrier ----
        __syncthreads();
        if (tid == 0) {
            __threadfence();
            *(volatile unsigned*)&g_flags[blk * 8] = (unsigned)(t + 1);
        }
        if (tid < GRID2) {
            while (*(volatile unsigned*)&g_flags[tid * 8] < (unsigned)(t + 1)) { }
            __threadfence();
        }
        __syncthreads();
    }
}

// ---------------------------------------------------------------------------
extern "C" void kernel_launch(void* const* d_in, const int* in_sizes, int n_in,
                              void* d_out, int out_size)
{
    const float* x   = (const float*)d_in[0];
    const float* Wxi = (const float*)d_in[1];
    const float* Whi = (const float*)d_in[2];
    const float* bi  = (const float*)d_in[3];
    const float* Wxf = (const float*)d_in[4];
    const float* Whf = (const float*)d_in[5];
    const float* bf  = (const float*)d_in[6];
    const float* Wxc = (const float*)d_in[7];
    const float* Whc = (const float*)d_in[8];
    const float* bc  = (const float*)d_in[9];
    const float* Wxo = (const float*)d_in[10];
    const float* Who = (const float*)d_in[11];
    const float* bo  = (const float*)d_in[12];
    float* out = (float*)d_out;

    cudaFuncSetAttribute(lstm_xproj, cudaFuncAttributeMaxDynamicSharedMemorySize, P1_SMEM);
    cudaFuncSetAttribute(lstm_rec,   cudaFuncAttributeMaxDynamicSharedMemorySize, SMEM2_BYTES);

    dim3 g1(32, 256);
    lstm_xproj<<<g1, 256, P1_SMEM>>>(x, Wxi, Wxf, Wxc, Wxo, bi, bf, bc, bo);

    lstm_rec<<<GRID2, 512, SMEM2_BYTES>>>(Whi, Whf, Whc, Who, out);
}

// round 3
// speedup vs baseline: 2.5282x; 1.5282x over previous
#include <cuda_runtime.h>
#include <cstdint>
#include <cstddef>

#define NB 64
#define NT 512
#define NH 1024
#define GRID2 128

#define GATE_STRIDE 33554432u  // 512*64*1024

__device__ float    g_gates[4u * GATE_STRIDE];  // [gate][t][b][h]
__device__ unsigned g_hA[2][NB * NH];           // h in tf32, MMA-fragment order, double-buffered
__device__ unsigned g_flags[GRID2 * 8];         // per-CTA barrier flags (32B apart)

__device__ __forceinline__ unsigned f2tf(float f) {
    unsigned r;
    asm("cvt.rna.tf32.f32 %0, %1;" : "=r"(r) : "f"(f));
    return r;
}

__device__ __forceinline__ void mma8(float c[4], const unsigned a[4], const unsigned b[2]) {
    asm volatile(
        "mma.sync.aligned.m16n8k8.row.col.f32.tf32.tf32.f32 "
        "{%0,%1,%2,%3},{%4,%5,%6,%7},{%8,%9},{%0,%1,%2,%3};\n"
        : "+f"(c[0]), "+f"(c[1]), "+f"(c[2]), "+f"(c[3])
        : "r"(a[0]), "r"(a[1]), "r"(a[2]), "r"(a[3]), "r"(b[0]), "r"(b[1]));
}

__device__ __forceinline__ void cp16(unsigned dst, const float* src) {
    asm volatile("cp.async.ca.shared.global [%0], [%1], 16;\n" :: "r"(dst), "l"(src));
}

__device__ __forceinline__ float sig_f(float z) {
    return __fdividef(1.0f, 1.0f + __expf(-z));
}
__device__ __forceinline__ float tanh_f(float z) {
    return __fdividef(2.0f, 1.0f + __expf(-2.0f * z)) - 1.0f;
}

// ---------------------------------------------------------------------------
// Phase 1: gate preactivations  g_gates[g][t][b][h] = x @ W_xg + b_g
// M=32768, N=4096 (4 gates x 1024), K=1024. cp.async double-buffered.
// Block tile 128x128x32, 256 threads, warp tile 64x32. Block(0,0) inits
// the recurrence state for this replay.
// ---------------------------------------------------------------------------
#define P1_SA 36
#define P1_SB 136
#define P1_SMEM ((2 * 128 * P1_SA + 2 * 32 * P1_SB) * 4)

__global__ void __launch_bounds__(256, 2) lstm_xproj(
    const float* __restrict__ x,
    const float* __restrict__ Wxi, const float* __restrict__ Wxf,
    const float* __restrict__ Wxc, const float* __restrict__ Wxo,
    const float* __restrict__ bi,  const float* __restrict__ bf,
    const float* __restrict__ bc,  const float* __restrict__ bo)
{
    extern __shared__ float p1s[];
    float* As = p1s;
    float* Bs = p1s + 2 * 128 * P1_SA;

    const int tid = threadIdx.x;

    // per-replay init: h0 fragments = 0, barrier flags = 0
    if (blockIdx.x == 0 && blockIdx.y == 0) {
        uint4 z4 = make_uint4(0u, 0u, 0u, 0u);
        uint4* hb4 = (uint4*)g_hA[0];
#pragma unroll 4
        for (int i = tid; i < (NB * NH) / 4; i += 256) hb4[i] = z4;
        for (int i = tid; i < GRID2 * 8; i += 256) g_flags[i] = 0u;
    }

    const int lane = tid & 31;
    const int w    = tid >> 5;
    const int mi   = w & 1;
    const int nj   = w >> 1;

    const int mblk  = blockIdx.y;
    const int nglob = blockIdx.x * 128;
    const int gate  = nglob >> 10;
    const int hbase = nglob & 1023;

    const float* W    = (gate == 0) ? Wxi : (gate == 1) ? Wxf : (gate == 2) ? Wxc : Wxo;
    const float* bias = (gate == 0) ? bi  : (gate == 1) ? bf  : (gate == 2) ? bc  : bo;

    const int a_row = tid >> 3, a_c4 = tid & 7;
    const int b_k   = tid >> 5, b_c4 = tid & 31;
    const unsigned As_u = (unsigned)__cvta_generic_to_shared(As);
    const unsigned Bs_u = (unsigned)__cvta_generic_to_shared(Bs);

    float acc[4][4][4];
#pragma unroll
    for (int a = 0; a < 4; a++)
#pragma unroll
        for (int b = 0; b < 4; b++)
#pragma unroll
            for (int c = 0; c < 4; c++) acc[a][b][c] = 0.0f;

    {
#pragma unroll
        for (int i = 0; i < 4; i++) {
            int row = a_row + 32 * i;
            cp16(As_u + (row * P1_SA + a_c4 * 4) * 4,
                 x + (size_t)(mblk * 128 + row) * 1024 + a_c4 * 4);
            int k = b_k + 8 * i;
            cp16(Bs_u + (k * P1_SB + b_c4 * 4) * 4,
                 W + (size_t)k * 1024 + hbase + b_c4 * 4);
        }
        asm volatile("cp.async.commit_group;\n");
    }

#pragma unroll 1
    for (int kt = 0; kt < 32; ++kt) {
        asm volatile("cp.async.wait_group 0;\n");
        __syncthreads();

        if (kt + 1 < 32) {
            int s = (kt + 1) & 1;
#pragma unroll
            for (int i = 0; i < 4; i++) {
                int row = a_row + 32 * i;
                cp16(As_u + (s * 128 * P1_SA + row * P1_SA + a_c4 * 4) * 4,
                     x + (size_t)(mblk * 128 + row) * 1024 + (kt + 1) * 32 + a_c4 * 4);
                int k = b_k + 8 * i;
                cp16(Bs_u + (s * 32 * P1_SB + k * P1_SB + b_c4 * 4) * 4,
                     W + (size_t)((kt + 1) * 32 + k) * 1024 + hbase + b_c4 * 4);
            }
            asm volatile("cp.async.commit_group;\n");
        }

        const float* Ab = As + (kt & 1) * 128 * P1_SA;
        const float* Bb = Bs + (kt & 1) * 32 * P1_SB;

#pragma unroll
        for (int q = 0; q < 4; q++) {
            const int kk = q * 8;
            unsigned afr[4][4], bfr[4][2];
#pragma unroll
            for (int mt = 0; mt < 4; mt++) {
                int r = mi * 64 + mt * 16 + (lane >> 2);
                int c = kk + (lane & 3);
                afr[mt][0] = f2tf(Ab[r * P1_SA + c]);
                afr[mt][1] = f2tf(Ab[(r + 8) * P1_SA + c]);
                afr[mt][2] = f2tf(Ab[r * P1_SA + c + 4]);
                afr[mt][3] = f2tf(Ab[(r + 8) * P1_SA + c + 4]);
            }
#pragma unroll
            for (int nt = 0; nt < 4; nt++) {
                int nb = nj * 32 + nt * 8 + (lane >> 2);
                int kr = kk + (lane & 3);
                bfr[nt][0] = f2tf(Bb[kr * P1_SB + nb]);
                bfr[nt][1] = f2tf(Bb[(kr + 4) * P1_SB + nb]);
            }
#pragma unroll
            for (int mt = 0; mt < 4; mt++)
#pragma unroll
                for (int nt = 0; nt < 4; nt++)
                    mma8(acc[mt][nt], afr[mt], bfr[nt]);
        }
    }

    float* gbuf = g_gates + (size_t)gate * GATE_STRIDE;
#pragma unroll
    for (int mt = 0; mt < 4; mt++) {
#pragma unroll
        for (int nt = 0; nt < 4; nt++) {
#pragma unroll
            for (int rr = 0; rr < 2; rr++) {
                int m   = mblk * 128 + mi * 64 + mt * 16 + (lane >> 2) + rr * 8;
                int col = nj * 32 + nt * 8 + (lane & 3) * 2;
                int h   = hbase + col;
                int b   = m >> 9;
                int t   = m & 511;
                float2 o;
                o.x = acc[mt][nt][rr * 2 + 0] + __ldg(bias + h);
                o.y = acc[mt][nt][rr * 2 + 1] + __ldg(bias + h + 1);
                *(float2*)(gbuf + (size_t)t * 65536 + (size_t)b * 1024 + h) = o;
            }
        }
    }
}

// ---------------------------------------------------------------------------
// Phase 2: persistent recurrence. 128 CTAs x 512 threads. CTA owns h-cols
// [blk*8, blk*8+8) across 4 gates (N=32). W_h in SMEM (tf32). h state kept
// in global in MMA-fragment order (tf32 at producer): consumers LDG.128
// fragments directly from L2 — no STS/LDS/cvt/syncs in the K loop.
// 16 warps = 4 m-tiles x 4 K-groups, warp tile m16n32.
// ---------------------------------------------------------------------------
#define P2_SW 40
#define P2_SZ 36
#define SMEM2_BYTES ((1024 * P2_SW + 2 * 64 * P2_SZ + 512) * 4)

__global__ void __launch_bounds__(512, 1) lstm_rec(
    const float* __restrict__ Whi, const float* __restrict__ Whf,
    const float* __restrict__ Whc, const float* __restrict__ Who,
    float* __restrict__ out)
{
    extern __shared__ unsigned char smem_raw[];
    unsigned* Wsm = (unsigned*)smem_raw;           // [1024][P2_SW]
    float*    zsm = (float*)(Wsm + 1024 * P2_SW);  // [2][64][P2_SZ]
    float*    csm = zsm + 2 * 64 * P2_SZ;          // [512]

    const int tid  = threadIdx.x;
    const int lane = tid & 31;
    const int w    = tid >> 5;
    const int mi   = w & 3;    // m base = mi*16
    const int ks   = w >> 2;   // K group
    const int blk  = blockIdx.x;
    const int hb   = blk * 8;

    // weight slice -> SMEM (tf32), once
    {
        const float* Wg[4] = {Whi, Whf, Whc, Who};
        for (int idx = tid; idx < 4096; idx += 512) {
            int g = idx >> 10, k = idx & 1023;
            const float* src = Wg[g] + (size_t)k * 1024 + hb;
            float4 v0 = *(const float4*)(src);
            float4 v1 = *(const float4*)(src + 4);
            unsigned* d = &Wsm[k * P2_SW + g * 8];
            d[0] = f2tf(v0.x); d[1] = f2tf(v0.y); d[2] = f2tf(v0.z); d[3] = f2tf(v0.w);
            d[4] = f2tf(v1.x); d[5] = f2tf(v1.y); d[6] = f2tf(v1.z); d[7] = f2tf(v1.w);
        }
        csm[tid] = 0.0f;
    }

    // consumer fragment-load base (words): slot S = ((ch*4+ks)*2+q)*4+mi,
    // word addr = S*128 + lane*4 (+j in uint4)
    const int cbase = ks * 1024 + mi * 128 + lane * 4;   // ch stride 4096, q stride 512

    // elementwise coords + producer scatter address
    const int em = tid >> 3, ej = tid & 7;
    const int hcol = hb + ej;
    int p_widx;
    {
        int row = em, col = hcol;
        int pmi = row >> 4, rb = row & 15, hi_r = rb >> 3, lr = rb & 7;
        int pch = col >> 6, pks = (col >> 4) & 3, pq = (col >> 3) & 1;
        int hi_c = (col >> 2) & 1, l2 = col & 3;
        int plane = lr * 4 + l2;
        int j = hi_r + 2 * hi_c;
        int S = ((pch * 4 + pks) * 2 + pq) * 4 + pmi;
        p_widx = S * 128 + plane * 4 + j;
    }

    __syncthreads();

#pragma unroll 1
    for (int t = 0; t < NT; ++t) {
        const unsigned* hA = g_hA[t & 1];
        unsigned*       hN = g_hA[(t + 1) & 1];

        // prefetch this step's gate preactivations
        const size_t gidx = (size_t)t * 65536 + (size_t)em * 1024 + hcol;
        const float gi = __ldg(g_gates + gidx);
        const float gf = __ldg(g_gates + GATE_STRIDE + gidx);
        const float gc = __ldg(g_gates + 2u * GATE_STRIDE + gidx);
        const float go = __ldg(g_gates + 3u * GATE_STRIDE + gidx);

        float acc[4][4];
#pragma unroll
        for (int a = 0; a < 4; a++)
#pragma unroll
            for (int c = 0; c < 4; c++) acc[a][c] = 0.0f;

        // depth-4 register prefetch of a-fragments (L2-resident, __ldcg)
        uint4 abuf[4][2];
#pragma unroll
        for (int p = 0; p < 4; p++) {
            abuf[p][0] = __ldcg((const uint4*)(hA + cbase + p * 4096));
            abuf[p][1] = __ldcg((const uint4*)(hA + cbase + p * 4096 + 512));
        }

#pragma unroll
        for (int ch = 0; ch < 16; ++ch) {
            uint4 n0, n1;
            if (ch + 4 < 16) {
                n0 = __ldcg((const uint4*)(hA + cbase + (ch + 4) * 4096));
                n1 = __ldcg((const uint4*)(hA + cbase + (ch + 4) * 4096 + 512));
            }
#pragma unroll
            for (int q = 0; q < 2; q++) {
                const uint4 av = abuf[ch & 3][q];
                unsigned afr[4] = {av.x, av.y, av.z, av.w};
                const int kg = ch * 64 + ks * 16 + q * 8 + (lane & 3);
#pragma unroll
                for (int nt = 0; nt < 4; nt++) {
                    const int nb = nt * 8 + (lane >> 2);
                    unsigned bfr[2];
                    bfr[0] = Wsm[kg * P2_SW + nb];
                    bfr[1] = Wsm[(kg + 4) * P2_SW + nb];
                    mma8(acc[nt], afr, bfr);
                }
            }
            if (ch + 4 < 16) {
                abuf[ch & 3][0] = n0;
                abuf[ch & 3][1] = n1;
            }
        }

        // K-group reduction via zsm (two phases)
        __syncthreads();
        if (ks < 2) {
            float* z = zsm + ks * 64 * P2_SZ;
#pragma unroll
            for (int nt = 0; nt < 4; nt++)
#pragma unroll
                for (int rr = 0; rr < 2; rr++) {
                    int r = mi * 16 + (lane >> 2) + rr * 8;
                    int c = nt * 8 + (lane & 3) * 2;
                    z[r * P2_SZ + c]     = acc[nt][rr * 2 + 0];
                    z[r * P2_SZ + c + 1] = acc[nt][rr * 2 + 1];
                }
        }
        __syncthreads();
        if (ks >= 2) {
            float* z = zsm + (ks - 2) * 64 * P2_SZ;
#pragma unroll
            for (int nt = 0; nt < 4; nt++)
#pragma unroll
                for (int rr = 0; rr < 2; rr++) {
                    int r = mi * 16 + (lane >> 2) + rr * 8;
                    int c = nt * 8 + (lane & 3) * 2;
                    z[r * P2_SZ + c]     += acc[nt][rr * 2 + 0];
                    z[r * P2_SZ + c + 1] += acc[nt][rr * 2 + 1];
                }
        }
        __syncthreads();

        // elementwise LSTM cell update: one element per thread
        {
            const float* z0 = zsm + em * P2_SZ;
            const float* z1 = zsm + 64 * P2_SZ + em * P2_SZ;
            float zi = z0[ej]      + z1[ej]      + gi;
            float zf = z0[8 + ej]  + z1[8 + ej]  + gf;
            float zc = z0[16 + ej] + z1[16 + ej] + gc;
            float zo = z0[24 + ej] + z1[24 + ej] + go;
            float iv = sig_f(zi);
            float fv = sig_f(zf);
            float cv = tanh_f(zc);
            float ov = sig_f(zo);
            float cnew = fv * csm[tid] + iv * cv;
            csm[tid] = cnew;
            float hv = ov * tanh_f(cnew);
            hN[p_widx] = f2tf(hv);   // tf32, fragment-ordered, converted ONCE
            out[(size_t)em * 524288 + (size_t)t * 1024 + hcol] = hv;
            if (t == NT - 1) {
                out[33554432u + (size_t)em * 1024 + hcol] = hv;
                out[33554432u + 65536u + (size_t)em * 1024 + hcol] = cnew;
            }
        }

        // ---- distributed grid barrier ----
        __syncthreads();
        if (tid == 0) {
            __threadfence();
            *(volatile unsigned*)&g_flags[blk * 8] = (unsigned)(t + 1);
        }
        if (tid < GRID2) {
            while (*(volatile unsigned*)&g_flags[tid * 8] < (unsigned)(t + 1)) { }
            __threadfence();
        }
        __syncthreads();
    }
}

// ---------------------------------------------------------------------------
extern "C" void kernel_launch(void* const* d_in, const int* in_sizes, int n_in,
                              void* d_out, int out_size)
{
    const float* x   = (const float*)d_in[0];
    const float* Wxi = (const float*)d_in[1];
    const float* Whi = (const float*)d_in[2];
    const float* bi  = (const float*)d_in[3];
    const float* Wxf = (const float*)d_in[4];
    const float* Whf = (const float*)d_in[5];
    const float* bf  = (const float*)d_in[6];
    const float* Wxc = (const float*)d_in[7];
    const float* Whc = (const float*)d_in[8];
    const float* bc  = (const float*)d_in[9];
    const float* Wxo = (const float*)d_in[10];
    const float* Who = (const float*)d_in[11];
    const float* bo  = (const float*)d_in[12];
    float* out = (float*)d_out;

    cudaFuncSetAttribute(lstm_xproj, cudaFuncAttributeMaxDynamicSharedMemorySize, P1_SMEM);
    cudaFuncSetAttribute(lstm_rec,   cudaFuncAttributeMaxDynamicSharedMemorySize, SMEM2_BYTES);

    dim3 g1(32, 256);
    lstm_xproj<<<g1, 256, P1_SMEM>>>(x, Wxi, Wxf, Wxc, Wxo, bi, bf, bc, bo);

    lstm_rec<<<GRID2, 512, SMEM2_BYTES>>>(Whi, Whf, Whc, Who, out);
}